// round 6
// baseline (speedup 1.0000x reference)
#include <cuda_runtime.h>
#include <cstdint>
#include <math.h>

// ---------------------------------------------------------------------------
// Qwen3 attention block. Round 6: GEMM fragment loads via ldmatrix.
//   - weights pre-transposed to [N][K] (+tf32 round) so BOTH operands are
//     k-major -> every mma fragment is one ldmatrix.x4 (32 LDSM vs 128 MMA
//     per k-iter, was 128 scalar LDS).
//   - hidden pre-rounded; flash epilogue emits tf32-rounded output.
//   - 3-stage cp.async pipeline unchanged; flash/norm unchanged.
// ---------------------------------------------------------------------------

#define T_SEQ 2048
#define HID   4096
#define NQH   32
#define NKV   8
#define HD    128
#define QKV_N 6144
#define O_N   4096

__device__ float g_qkv[(size_t)T_SEQ * QKV_N];
__device__ float g_attn[(size_t)T_SEQ * O_N];
__device__ float g_hidr[(size_t)T_SEQ * HID];
__device__ float g_wqkvT[(size_t)QKV_N * HID];   // [N][K], tf32-rounded
__device__ float g_woT[(size_t)O_N * HID];       // [N][K], tf32-rounded

__device__ __forceinline__ float f2tf32(float x) {
    uint32_t u;
    asm("cvt.rna.tf32.f32 %0, %1;" : "=r"(u) : "f"(x));
    return __uint_as_float(u);
}

__device__ __forceinline__ void mma8u(float& c0, float& c1, float& c2, float& c3,
                                      uint32_t a0, uint32_t a1, uint32_t a2, uint32_t a3,
                                      uint32_t b0, uint32_t b1) {
    asm volatile(
        "mma.sync.aligned.m16n8k8.row.col.f32.tf32.tf32.f32 "
        "{%0,%1,%2,%3}, {%4,%5,%6,%7}, {%8,%9}, {%0,%1,%2,%3};\n"
        : "+f"(c0), "+f"(c1), "+f"(c2), "+f"(c3)
        : "r"(a0), "r"(a1), "r"(a2), "r"(a3), "r"(b0), "r"(b1));
}

__device__ __forceinline__ void mma8(float& c0, float& c1, float& c2, float& c3,
                                     float a0, float a1, float a2, float a3,
                                     float b0, float b1) {
    mma8u(c0, c1, c2, c3,
          __float_as_uint(a0), __float_as_uint(a1),
          __float_as_uint(a2), __float_as_uint(a3),
          __float_as_uint(b0), __float_as_uint(b1));
}

__device__ __forceinline__ void ldsm4(uint32_t& r0, uint32_t& r1,
                                      uint32_t& r2, uint32_t& r3, uint32_t addr) {
    asm volatile("ldmatrix.sync.aligned.m8n8.x4.shared.b16 {%0,%1,%2,%3}, [%4];"
                 : "=r"(r0), "=r"(r1), "=r"(r2), "=r"(r3) : "r"(addr));
}

__device__ __forceinline__ uint32_t s2u(const void* p) {
    return (uint32_t)__cvta_generic_to_shared(p);
}
#define CPASYNC16(dst_u32, src_ptr) \
    asm volatile("cp.async.cg.shared.global [%0], [%1], 16;\n" \
                 :: "r"(dst_u32), "l"(src_ptr))

// ---------------------------------------------------------------------------
// Pipelined GEMM: C[M,N] = A[M,K] @ BT[N,K]^T, both operands k-major tf32.
// Block 128x256, BK=32, 256 threads (8 warps, 2M x 4N, warp tile 64x64).
// smem rows stride 36 words: ldmatrix row addresses land in distinct 16B
// banks (9r mod 8 = r). 3-stage cp.async.
// ---------------------------------------------------------------------------
#define BM 128
#define BN 256
#define BK 32
#define TSTRD 36
#define STG_FLOATS ((BM + BN) * TSTRD)                  // 13824
#define GEMM_SMEM (3 * STG_FLOATS * 4)                  // 165888 B

__global__ __launch_bounds__(256, 1)
void gemm_tf32_pipe(const float* __restrict__ A, const float* __restrict__ BT,
                    float* __restrict__ C, int M, int N, int K) {
    extern __shared__ float sm[];

    const int tid  = threadIdx.x;
    const int warp = tid >> 5, lane = tid & 31;
    const int tq = lane >> 2, tr = lane & 3;
    const int wm = (warp & 1) * 64;
    const int wn = (warp >> 1) * 64;
    const size_t bm = (size_t)blockIdx.x * BM;
    const size_t bn = (size_t)blockIdx.y * BN;

    // ldmatrix per-lane offsets: mat = lane>>3 selects sub-matrix, rin row
    const int rin = lane & 7, mat = lane >> 3;
    const int a_row_off = rin + (mat & 1) * 8;       // + wm + 16*mi
    const int a_col_off = (mat >> 1) * 4;            // + 8*kk
    const int b_row_off = rin + (mat >> 1) * 8;      // + wn + 16*p
    const int b_col_off = (mat & 1) * 4;             // + 8*kk

    float c[4][8][4];
    #pragma unroll
    for (int mi = 0; mi < 4; mi++)
        #pragma unroll
        for (int ni = 0; ni < 8; ni++)
            #pragma unroll
            for (int e = 0; e < 4; e++) c[mi][ni][e] = 0.f;

    const int NT = K / BK;

    // staging: A 128 rows x 32k (4 chunks/thr), BT 256 rows x 32k (8 chunks/thr)
    auto stage = [&](int kt, int s) {
        float* sa = sm + s * STG_FLOATS;
        float* sb = sa + BM * TSTRD;
        #pragma unroll
        for (int i = 0; i < 4; i++) {
            int cidx = tid + 256 * i;
            int row = cidx >> 3, kc = (cidx & 7) * 4;
            CPASYNC16(s2u(sa + row * TSTRD + kc),
                      A + (bm + row) * (size_t)K + kt + kc);
        }
        #pragma unroll
        for (int i = 0; i < 8; i++) {
            int cidx = tid + 256 * i;
            int row = cidx >> 3, kc = (cidx & 7) * 4;
            CPASYNC16(s2u(sb + row * TSTRD + kc),
                      BT + (bn + row) * (size_t)K + kt + kc);
        }
        asm volatile("cp.async.commit_group;\n");
    };

    stage(0, 0);
    stage(BK, 1);

    for (int t = 0; t < NT; t++) {
        __syncthreads();
        if (t + 2 < NT) {
            stage((t + 2) * BK, (t + 2) % 3);
            asm volatile("cp.async.wait_group 2;\n");
        } else if (t + 1 < NT) {
            asm volatile("cp.async.wait_group 1;\n");
        } else {
            asm volatile("cp.async.wait_group 0;\n");
        }
        __syncthreads();

        const float* sa = sm + (t % 3) * STG_FLOATS;
        const uint32_t saU = s2u(sa);
        const uint32_t sbU = saU + BM * TSTRD * 4;

        #pragma unroll
        for (int kk = 0; kk < 4; kk++) {
            uint32_t a[4][4];
            #pragma unroll
            for (int mi = 0; mi < 4; mi++) {
                uint32_t addr = saU +
                    ((wm + 16 * mi + a_row_off) * TSTRD + 8 * kk + a_col_off) * 4;
                ldsm4(a[mi][0], a[mi][1], a[mi][2], a[mi][3], addr);
            }
            uint32_t b[8][2];
            #pragma unroll
            for (int p = 0; p < 4; p++) {
                uint32_t addr = sbU +
                    ((wn + 16 * p + b_row_off) * TSTRD + 8 * kk + b_col_off) * 4;
                ldsm4(b[2*p][0], b[2*p][1], b[2*p+1][0], b[2*p+1][1], addr);
            }
            #pragma unroll
            for (int mi = 0; mi < 4; mi++)
                #pragma unroll
                for (int ni = 0; ni < 8; ni++)
                    mma8u(c[mi][ni][0], c[mi][ni][1], c[mi][ni][2], c[mi][ni][3],
                          a[mi][0], a[mi][1], a[mi][2], a[mi][3],
                          b[ni][0], b[ni][1]);
        }
    }

    #pragma unroll
    for (int mi = 0; mi < 4; mi++) {
        #pragma unroll
        for (int ni = 0; ni < 8; ni++) {
            size_t r  = bm + wm + 16 * mi + tq;
            size_t cc = bn + wn + 8 * ni + 2 * tr;
            *(float2*)(C + r * N + cc)       = make_float2(c[mi][ni][0], c[mi][ni][1]);
            *(float2*)(C + (r + 8) * N + cc) = make_float2(c[mi][ni][2], c[mi][ni][3]);
        }
    }
}

// ---------------------------------------------------------------------------
// prepass kernels
// ---------------------------------------------------------------------------
__global__ void round_copy(const float* __restrict__ src, float* __restrict__ dst,
                           int n4) {
    int i = blockIdx.x * blockDim.x + threadIdx.x;
    if (i < n4) {
        float4 v = ((const float4*)src)[i];
        v.x = f2tf32(v.x); v.y = f2tf32(v.y); v.z = f2tf32(v.z); v.w = f2tf32(v.w);
        ((float4*)dst)[i] = v;
    }
}

// transpose + round: src[R][Cc] -> dst[Cc][R]
__global__ void transpose_round(const float* __restrict__ src, float* __restrict__ dst,
                                int R, int Cc) {
    __shared__ float tile[32][33];
    const int bx = blockIdx.x * 32, by = blockIdx.y * 32;
    const int x = threadIdx.x, y0 = threadIdx.y;
    #pragma unroll
    for (int j = 0; j < 32; j += 8)
        tile[y0 + j][x] = src[(size_t)(by + y0 + j) * Cc + bx + x];
    __syncthreads();
    #pragma unroll
    for (int j = 0; j < 32; j += 8)
        dst[(size_t)(bx + y0 + j) * R + by + x] = f2tf32(tile[x][y0 + j]);
}

// ---------------------------------------------------------------------------
// Per-(token, head) RMSNorm + RoPE (unchanged).
// ---------------------------------------------------------------------------
__global__ void norm_rope(const float* __restrict__ qw, const float* __restrict__ kw) {
    const int t = blockIdx.x;
    const int h = blockIdx.y;
    float* base = g_qkv + (size_t)t * QKV_N + h * HD;

    __shared__ float xs[HD];
    __shared__ float red[4];
    const int j = threadIdx.x;

    float x = base[j];
    xs[j] = x;
    float ss = x * x;
    #pragma unroll
    for (int o = 16; o > 0; o >>= 1) ss += __shfl_xor_sync(0xffffffffu, ss, o);
    if ((j & 31) == 0) red[j >> 5] = ss;
    __syncthreads();

    float scale = rsqrtf((red[0] + red[1] + red[2] + red[3]) * (1.0f / HD) + 1e-6f);
    const float* w = (h < NQH) ? qw : kw;

    if (j < 64) {
        float x1 = xs[j]      * scale * w[j];
        float x2 = xs[j + 64] * scale * w[j + 64];
        float invf = exp2f(-(float)j * (19.931568569324174f / 64.0f));
        float ang = (float)t * invf;
        float s, cth;
        sincosf(ang, &s, &cth);
        base[j]      = x1 * cth - x2 * s;
        base[j + 64] = x2 * cth + x1 * s;
    }
}

// ---------------------------------------------------------------------------
// Flash attention (unchanged; epilogue stores tf32-rounded output).
// ---------------------------------------------------------------------------
#define KSTR 132
#define VSTR 136
#define PSTR 68

__global__ __launch_bounds__(128)
void flash_attn() {
    extern __shared__ float sm[];
    float (*Ks)[KSTR] = (float(*)[KSTR])sm;
    float (*Vs)[VSTR] = (float(*)[VSTR])(sm + 64 * KSTR);
    float (*Ps)[PSTR] = (float(*)[PSTR])(sm + 64 * KSTR + 64 * VSTR);

    const int h  = blockIdx.x;
    const int qb = blockIdx.y;
    const int kh = h >> 2;
    const int tid = threadIdx.x;
    const int warp = tid >> 5, lane = tid & 31;
    const int tq = lane >> 2, tr = lane & 3;
    const float scaling = 0.08838834764831845f;

    #pragma unroll
    for (int i = 0; i < 16; i++) {
        int f = tid + 128 * i;
        int row = f >> 5, c4 = (f & 31) * 4;
        float4 v = *(const float4*)(g_qkv + (size_t)(64 * qb + row) * QKV_N + h * HD + c4);
        v.x = f2tf32(v.x * scaling); v.y = f2tf32(v.y * scaling);
        v.z = f2tf32(v.z * scaling); v.w = f2tf32(v.w * scaling);
        *(float4*)&Ks[row][c4] = v;
    }
    __syncthreads();
    float qf[16][4];
    #pragma unroll
    for (int kk = 0; kk < 16; kk++) {
        int r0 = 16 * warp + tq, k0 = 8 * kk + tr;
        qf[kk][0] = Ks[r0][k0];
        qf[kk][1] = Ks[r0 + 8][k0];
        qf[kk][2] = Ks[r0][k0 + 4];
        qf[kk][3] = Ks[r0 + 8][k0 + 4];
    }
    __syncthreads();

    float o[16][4];
    #pragma unroll
    for (int ni = 0; ni < 16; ni++)
        #pragma unroll
        for (int e = 0; e < 4; e++) o[ni][e] = 0.f;
    float m1 = -1e30f, m2 = -1e30f, l1 = 0.f, l2 = 0.f;

    const int r1 = 16 * warp + tq, r2 = r1 + 8;

    for (int kb = 0; kb <= qb; kb++) {
        #pragma unroll
        for (int i = 0; i < 16; i++) {
            int f = tid + 128 * i;
            int row = f >> 5, c4 = (f & 31) * 4;
            const float* rp = g_qkv + (size_t)(64 * kb + row) * QKV_N;
            float4 kv = *(const float4*)(rp + 4096 + kh * HD + c4);
            kv.x = f2tf32(kv.x); kv.y = f2tf32(kv.y); kv.z = f2tf32(kv.z); kv.w = f2tf32(kv.w);
            *(float4*)&Ks[row][c4] = kv;
            float4 vv = *(const float4*)(rp + 5120 + kh * HD + c4);
            vv.x = f2tf32(vv.x); vv.y = f2tf32(vv.y); vv.z = f2tf32(vv.z); vv.w = f2tf32(vv.w);
            *(float4*)&Vs[row][c4] = vv;
        }
        __syncthreads();

        float s[8][4];
        #pragma unroll
        for (int ni = 0; ni < 8; ni++)
            #pragma unroll
            for (int e = 0; e < 4; e++) s[ni][e] = 0.f;

        #pragma unroll
        for (int kk = 0; kk < 16; kk++) {
            const int d0 = 8 * kk + tr;
            #pragma unroll
            for (int ni = 0; ni < 8; ni++) {
                float b0 = Ks[8 * ni + tq][d0];
                float b1 = Ks[8 * ni + tq][d0 + 4];
                mma8(s[ni][0], s[ni][1], s[ni][2], s[ni][3],
                     qf[kk][0], qf[kk][1], qf[kk][2], qf[kk][3], b0, b1);
            }
        }

        if (kb == qb) {
            #pragma unroll
            for (int ni = 0; ni < 8; ni++) {
                int c0 = 8 * ni + 2 * tr;
                if (c0     > r1) s[ni][0] = -1e30f;
                if (c0 + 1 > r1) s[ni][1] = -1e30f;
                if (c0     > r2) s[ni][2] = -1e30f;
                if (c0 + 1 > r2) s[ni][3] = -1e30f;
            }
        }

        float tm1 = -1e30f, tm2 = -1e30f;
        #pragma unroll
        for (int ni = 0; ni < 8; ni++) {
            tm1 = fmaxf(tm1, fmaxf(s[ni][0], s[ni][1]));
            tm2 = fmaxf(tm2, fmaxf(s[ni][2], s[ni][3]));
        }
        tm1 = fmaxf(tm1, __shfl_xor_sync(0xffffffffu, tm1, 1));
        tm1 = fmaxf(tm1, __shfl_xor_sync(0xffffffffu, tm1, 2));
        tm2 = fmaxf(tm2, __shfl_xor_sync(0xffffffffu, tm2, 1));
        tm2 = fmaxf(tm2, __shfl_xor_sync(0xffffffffu, tm2, 2));

        float nm1 = fmaxf(m1, tm1), nm2 = fmaxf(m2, tm2);
        float a1 = __expf(m1 - nm1), a2 = __expf(m2 - nm2);

        float rs1 = 0.f, rs2 = 0.f;
        #pragma unroll
        for (int ni = 0; ni < 8; ni++) {
            int c0 = 8 * ni + 2 * tr;
            float p0 = __expf(s[ni][0] - nm1);
            float p1 = __expf(s[ni][1] - nm1);
            float p2 = __expf(s[ni][2] - nm2);
            float p3 = __expf(s[ni][3] - nm2);
            rs1 += p0 + p1; rs2 += p2 + p3;
            Ps[r1][c0]     = f2tf32(p0);
            Ps[r1][c0 + 1] = f2tf32(p1);
            Ps[r2][c0]     = f2tf32(p2);
            Ps[r2][c0 + 1] = f2tf32(p3);
        }
        rs1 += __shfl_xor_sync(0xffffffffu, rs1, 1);
        rs1 += __shfl_xor_sync(0xffffffffu, rs1, 2);
        rs2 += __shfl_xor_sync(0xffffffffu, rs2, 1);
        rs2 += __shfl_xor_sync(0xffffffffu, rs2, 2);

        l1 = l1 * a1 + rs1; l2 = l2 * a2 + rs2;
        m1 = nm1; m2 = nm2;

        #pragma unroll
        for (int ni = 0; ni < 16; ni++) {
            o[ni][0] *= a1; o[ni][1] *= a1;
            o[ni][2] *= a2; o[ni][3] *= a2;
        }

        __syncwarp();

        #pragma unroll
        for (int kp = 0; kp < 8; kp++) {
            float a0  = Ps[r1][8 * kp + tr];
            float a1f = Ps[r2][8 * kp + tr];
            float a2f = Ps[r1][8 * kp + tr + 4];
            float a3f = Ps[r2][8 * kp + tr + 4];
            #pragma unroll
            for (int ni = 0; ni < 16; ni++) {
                float b0 = Vs[8 * kp + tr][8 * ni + tq];
                float b1 = Vs[8 * kp + tr + 4][8 * ni + tq];
                mma8(o[ni][0], o[ni][1], o[ni][2], o[ni][3], a0, a1f, a2f, a3f, b0, b1);
            }
        }
        __syncthreads();
    }

    const float inv1 = 1.0f / l1, inv2 = 1.0f / l2;
    const size_t gr1 = (size_t)(64 * qb) + r1;
    #pragma unroll
    for (int ni = 0; ni < 16; ni++) {
        int d = 8 * ni + 2 * tr;
        *(float2*)(g_attn + gr1 * O_N + h * HD + d) =
            make_float2(f2tf32(o[ni][0] * inv1), f2tf32(o[ni][1] * inv1));
        *(float2*)(g_attn + (gr1 + 8) * O_N + h * HD + d) =
            make_float2(f2tf32(o[ni][2] * inv2), f2tf32(o[ni][3] * inv2));
    }
}

// ---------------------------------------------------------------------------
extern "C" void kernel_launch(void* const* d_in, const int* in_sizes, int n_in,
                              void* d_out, int out_size) {
    const float* hidden = (const float*)d_in[1];
    const float* w_qkv  = (const float*)d_in[2];
    const float* qw     = (const float*)d_in[3];
    const float* kw     = (const float*)d_in[4];
    const float* w_o    = (const float*)d_in[5];
    float* out = (float*)d_out;

    void *qkv_p = nullptr, *attn_p = nullptr, *hidr_p = nullptr;
    void *wqkvT_p = nullptr, *woT_p = nullptr;
    cudaGetSymbolAddress(&qkv_p, g_qkv);
    cudaGetSymbolAddress(&attn_p, g_attn);
    cudaGetSymbolAddress(&hidr_p, g_hidr);
    cudaGetSymbolAddress(&wqkvT_p, g_wqkvT);
    cudaGetSymbolAddress(&woT_p, g_woT);

    static bool attr_set = false;
    if (!attr_set) {
        cudaFuncSetAttribute(gemm_tf32_pipe,
                             cudaFuncAttributeMaxDynamicSharedMemorySize, GEMM_SMEM);
        const int SMEM_ATTN = (64 * KSTR + 64 * VSTR + 64 * PSTR) * 4;
        cudaFuncSetAttribute(flash_attn,
                             cudaFuncAttributeMaxDynamicSharedMemorySize, SMEM_ATTN);
        attr_set = true;
    }
    const int SMEM_ATTN = (64 * KSTR + 64 * VSTR + 64 * PSTR) * 4;  // 86016 B

    round_copy<<<(T_SEQ * HID / 4 + 255) / 256, 256>>>(
        hidden, (float*)hidr_p, T_SEQ * HID / 4);
    transpose_round<<<dim3(QKV_N / 32, HID / 32), dim3(32, 8)>>>(
        w_qkv, (float*)wqkvT_p, HID, QKV_N);
    transpose_round<<<dim3(O_N / 32, HID / 32), dim3(32, 8)>>>(
        w_o, (float*)woT_p, HID, O_N);

    gemm_tf32_pipe<<<dim3(T_SEQ / BM, QKV_N / BN), 256, GEMM_SMEM>>>(
        (const float*)hidr_p, (const float*)wqkvT_p, (float*)qkv_p,
        T_SEQ, QKV_N, HID);

    norm_rope<<<dim3(T_SEQ, NQH + NKV), HD>>>(qw, kw);

    flash_attn<<<dim3(NQH, T_SEQ / 64), 128, SMEM_ATTN>>>();

    gemm_tf32_pipe<<<dim3(T_SEQ / BM, O_N / BN), 256, GEMM_SMEM>>>(
        (const float*)attn_p, (const float*)woT_p, out,
        T_SEQ, O_N, HID);
}